// round 11
// baseline (speedup 1.0000x reference)
#include <cuda_runtime.h>
#include <cuda_fp16.h>
#include <math.h>

// Problem constants (fixed by reference setup_inputs):
//   n = 100000 nodes, seq_len = 4, hidden = 128, n_edges = 1.6M
#define MAX_N      100000
#define MAX_EDGES  1600000
#define HIDDEN     128
#define SEQ_STRIDE (4 * 128)   // floats per node in semantics

#define TPB        256         // threads per fused block (8 warps)
#define NPB        64          // nodes (rows) per block tile

// Scratch (device globals; no allocations allowed).
__device__ __half g_sem16[MAX_N * HIDDEN]; // fp16 copy of sem[:,0,:] (25.6 MB)
__device__ int g_cnt[MAX_N];          // per-target in-degree (histogram)
__device__ int g_off[MAX_N + 1];      // CSR-by-target offsets
__device__ int g_cursor[MAX_N];       // placement cursors
__device__ int g_srcs[MAX_EDGES];     // source ids sorted by target
__device__ int g_idx_is_64;           // 1 = int64 edge_index, 0 = int32

// ---------------------------------------------------------------------------
// f32x2 packed-FMA helpers.
// ---------------------------------------------------------------------------
__device__ __forceinline__ unsigned long long pack_f32x2(float lo, float hi) {
    unsigned long long r;
    asm("mov.b64 %0, {%1, %2};" : "=l"(r) : "f"(lo), "f"(hi));
    return r;
}
__device__ __forceinline__ unsigned long long pack_dup_f32x2(float v) {
    unsigned long long r;
    asm("mov.b64 %0, {%1, %1};" : "=l"(r) : "f"(v));
    return r;
}
__device__ __forceinline__ void fma_f32x2(unsigned long long& d,
                                          unsigned long long a,
                                          unsigned long long b) {
    asm("fma.rn.f32x2 %0, %1, %2, %0;" : "+l"(d) : "l"(a), "l"(b));
}
__device__ __forceinline__ void unpack_f32x2(unsigned long long v,
                                             float& lo, float& hi) {
    asm("mov.b64 {%0, %1}, %2;" : "=f"(lo), "=f"(hi) : "l"(v));
}

// ---------------------------------------------------------------------------
// Prep: dtype probe + zero g_cnt + convert sem[:,0,:] to fp16.
// ---------------------------------------------------------------------------
__global__ void prep_kernel(const float* __restrict__ sem,
                            const long long* __restrict__ ei64,
                            long long n, int n_nodes) {
    int tid = blockIdx.x * blockDim.x + threadIdx.x;
    int nt  = gridDim.x * blockDim.x;

    for (int i = tid; i < n_nodes; i += nt) g_cnt[i] = 0;

    const int n_oct = n_nodes * (HIDDEN / 8);
    for (int i = tid; i < n_oct; i += nt) {
        int node = i >> 4;           // 16 octs per node
        int oct  = i & 15;
        const float4* src = (const float4*)(sem + (size_t)node * SEQ_STRIDE + oct * 8);
        float4 a = __ldg(src);
        float4 b = __ldg(src + 1);
        __half2 h[4];
        h[0] = __floats2half2_rn(a.x, a.y);
        h[1] = __floats2half2_rn(a.z, a.w);
        h[2] = __floats2half2_rn(b.x, b.y);
        h[3] = __floats2half2_rn(b.z, b.w);
        *(uint4*)(g_sem16 + (size_t)node * HIDDEN + oct * 8) = *(uint4*)h;
    }

    if (blockIdx.x == 0 && threadIdx.x < 32) {
        int lane = threadIdx.x;
        int bad = 0;
        #pragma unroll
        for (int i = 0; i < 8; i++) {
            long long v = ei64[lane * 8 + i];
            if (v < 0 || v >= n) bad = 1;
        }
        unsigned m = __ballot_sync(0xFFFFFFFFu, bad);
        if (lane == 0) g_idx_is_64 = (m == 0u) ? 1 : 0;
    }
}

// ---------------------------------------------------------------------------
// Histogram of TARGET in-degree.
// ---------------------------------------------------------------------------
__global__ void hist_kernel(const void* __restrict__ ei_raw, int n_edges) {
    int e = blockIdx.x * blockDim.x + threadIdx.x;
    if (e >= n_edges) return;
    int tgt;
    if (g_idx_is_64) {
        longlong2 p = __ldg((const longlong2*)ei_raw + e);
        tgt = (int)p.y;
    } else {
        int2 p = __ldg((const int2*)ei_raw + e);
        tgt = p.y;
    }
    atomicAdd(&g_cnt[tgt], 1);
}

// ---------------------------------------------------------------------------
// Single-block exclusive scan over counts -> g_off, g_cursor.
// ---------------------------------------------------------------------------
#define SCAN_THREADS 1024
__global__ void scan_kernel(int n) {
    __shared__ int ssum[SCAN_THREADS];
    int t = threadIdx.x;
    int chunk = (n + SCAN_THREADS - 1) / SCAN_THREADS;
    int lo = t * chunk;
    int hi = min(lo + chunk, n);

    int sum = 0;
    for (int i = lo; i < hi; i++) sum += g_cnt[i];
    ssum[t] = sum;
    __syncthreads();

    for (int off = 1; off < SCAN_THREADS; off <<= 1) {
        int v = (t >= off) ? ssum[t - off] : 0;
        __syncthreads();
        ssum[t] += v;
        __syncthreads();
    }

    int run = (t == 0) ? 0 : ssum[t - 1];
    for (int i = lo; i < hi; i++) {
        int c = g_cnt[i];
        g_off[i] = run;
        g_cursor[i] = run;
        run += c;
    }
    if (t == SCAN_THREADS - 1) g_off[n] = run;
}

// ---------------------------------------------------------------------------
// Placement: bucket SOURCE ids by TARGET (counting sort on tgt).
// ---------------------------------------------------------------------------
__global__ void place_kernel(const void* __restrict__ ei_raw, int n_edges) {
    int e = blockIdx.x * blockDim.x + threadIdx.x;
    if (e >= n_edges) return;
    int src, tgt;
    if (g_idx_is_64) {
        longlong2 p = __ldg((const longlong2*)ei_raw + e);
        src = (int)p.x; tgt = (int)p.y;
    } else {
        int2 p = __ldg((const int2*)ei_raw + e);
        src = p.x; tgt = p.y;
    }
    int pos = atomicAdd(&g_cursor[tgt], 1);
    g_srcs[pos] = src;
}

// ---------------------------------------------------------------------------
// Fused gather(fp16, 2 edges per warp-LDG.128) + GEMM(fp32) + GELU.
// 64 nodes/block, 256 threads, 96 KB smem.
//
// Gather: warp per node; lanes 0-15 fetch edge A's 256 B row (uint4/lane),
//         lanes 16-31 fetch edge B's in the SAME LDG -> warp-LDG count per
//         edge is halved. 4-deep unroll = 8 edges in flight. Per node, one
//         shfl_xor(16) pass folds the two parities together.
// sA layout: element (k, m) at sA[k*64 + (m ^ (k>>3))]; gather STS uses
//         sub = k>>3 (16 lanes, distinct banks); GEMM reads are warp-uniform.
// GEMM:   warp owns 2 rows x 128 cols per pass (4 passes); per k: 2 uniform
//         LDS.32 (a), 1 LDS.128 (W, conflict-free), 4 FFMA2.
// Epilogue: exact GELU, fully coalesced STG.128 (warp writes one row chunk).
// ---------------------------------------------------------------------------
extern __shared__ float dsm[];

__global__ void __launch_bounds__(TPB)
agg_gemm_gelu_kernel(const float* __restrict__ W,
                     float* __restrict__ out,
                     int n) {
    float* sB = dsm;                    // [128*128] W row-major
    float* sA = dsm + HIDDEN * HIDDEN;  // [128*64] k-major, swizzled

    const int w      = threadIdx.x >> 5;
    const int lane   = threadIdx.x & 31;
    const int half16 = lane >> 4;       // edge parity
    const int sub    = lane & 15;       // position within row (8 halfs each)
    const int base   = blockIdx.x * NPB;

    // ---- Stage W ----
    {
        const float4* Wv = (const float4*)W;
        float4* sBv = (float4*)sB;
        #pragma unroll
        for (int i = 0; i < (HIDDEN * HIDDEN / 4) / TPB; i++)
            sBv[threadIdx.x + i * TPB] = __ldg(Wv + threadIdx.x + i * TPB);
    }

    // ---- Gather phase: warp w handles nodes base + w, w+8, ..., w+56 ----
    for (int q = 0; q < NPB / 8; q++) {
        const int r    = q * 8 + w;       // local row 0..63
        const int node = base + r;
        float acc[8];
        #pragma unroll
        for (int i = 0; i < 8; i++) acc[i] = 0.f;
        float inv = 0.f;

        if (node < n) {
            const int beg = g_off[node];
            const int end = g_off[node + 1];
            inv = 1.0f / (float)max(end - beg, 1);

            int e = beg;
            for (; e + 8 <= end; e += 8) {
                int idx[4];
                #pragma unroll
                for (int u = 0; u < 4; u++)
                    idx[u] = __ldg(g_srcs + e + 2 * u + half16);
                uint4 v[4];
                #pragma unroll
                for (int u = 0; u < 4; u++)
                    v[u] = __ldg((const uint4*)(g_sem16 + (size_t)idx[u] * HIDDEN) + sub);
                #pragma unroll
                for (int u = 0; u < 4; u++) {
                    const __half2* h = (const __half2*)&v[u];
                    #pragma unroll
                    for (int p = 0; p < 4; p++) {
                        float2 f = __half22float2(h[p]);
                        acc[2 * p]     += f.x;
                        acc[2 * p + 1] += f.y;
                    }
                }
            }
            for (; e + 2 <= end; e += 2) {
                int i0 = __ldg(g_srcs + e + half16);
                uint4 v0 = __ldg((const uint4*)(g_sem16 + (size_t)i0 * HIDDEN) + sub);
                const __half2* h = (const __half2*)&v0;
                #pragma unroll
                for (int p = 0; p < 4; p++) {
                    float2 f = __half22float2(h[p]);
                    acc[2 * p]     += f.x;
                    acc[2 * p + 1] += f.y;
                }
            }
            if (e < end && half16 == 0) {
                int i0 = __ldg(g_srcs + e);
                uint4 v0 = __ldg((const uint4*)(g_sem16 + (size_t)i0 * HIDDEN) + sub);
                const __half2* h = (const __half2*)&v0;
                #pragma unroll
                for (int p = 0; p < 4; p++) {
                    float2 f = __half22float2(h[p]);
                    acc[2 * p]     += f.x;
                    acc[2 * p + 1] += f.y;
                }
            }
        }

        // Fold the two edge parities together.
        #pragma unroll
        for (int i = 0; i < 8; i++)
            acc[i] += __shfl_xor_sync(0xFFFFFFFFu, acc[i], 16);

        // Store mean into swizzled sA (lanes 0-15 only; k = 8*sub + i).
        if (half16 == 0) {
            const int ms = r ^ sub;
            #pragma unroll
            for (int i = 0; i < 8; i++)
                sA[(8 * sub + i) * NPB + ms] = acc[i] * inv;
        }
    }
    __syncthreads();

    // ---- GEMM phase: 4 passes, warp owns rows (p*16 + 2w, +1), cols lane*4..+3
    #pragma unroll
    for (int p = 0; p < 4; p++) {
        const int r0 = p * 16 + 2 * w;
        unsigned long long acc2[2][2] = {{0ull, 0ull}, {0ull, 0ull}};

        #pragma unroll 8
        for (int k = 0; k < HIDDEN; k++) {
            const int sw = k >> 3;
            unsigned long long a0 = pack_dup_f32x2(sA[k * NPB + (r0 ^ sw)]);
            unsigned long long a1 = pack_dup_f32x2(sA[k * NPB + ((r0 + 1) ^ sw)]);
            float4 wk = *(const float4*)&sB[k * HIDDEN + lane * 4];
            unsigned long long w01 = pack_f32x2(wk.x, wk.y);
            unsigned long long w23 = pack_f32x2(wk.z, wk.w);
            fma_f32x2(acc2[0][0], a0, w01);
            fma_f32x2(acc2[0][1], a0, w23);
            fma_f32x2(acc2[1][0], a1, w01);
            fma_f32x2(acc2[1][1], a1, w23);
        }

        #pragma unroll
        for (int mi = 0; mi < 2; mi++) {
            int row = base + r0 + mi;
            if (row < n) {
                float4 o;
                unpack_f32x2(acc2[mi][0], o.x, o.y);
                unpack_f32x2(acc2[mi][1], o.z, o.w);
                o.x = 0.5f * o.x * (1.0f + erff(o.x * 0.70710678118654752f));
                o.y = 0.5f * o.y * (1.0f + erff(o.y * 0.70710678118654752f));
                o.z = 0.5f * o.z * (1.0f + erff(o.z * 0.70710678118654752f));
                o.w = 0.5f * o.w * (1.0f + erff(o.w * 0.70710678118654752f));
                // coalesced: warp covers 512 B of this row
                *(float4*)(out + (size_t)row * HIDDEN + lane * 4) = o;
            }
        }
    }
}

// ---------------------------------------------------------------------------
// kernel_launch: prep -> hist -> scan -> place -> fused.
// All async on the default stream; graph-capturable; no allocations.
// Input order (metadata): semantics, attention_masks (unused), W, edge_index.
// ---------------------------------------------------------------------------
extern "C" void kernel_launch(void* const* d_in, const int* in_sizes, int n_in,
                              void* d_out, int out_size) {
    const float* sem = (const float*)d_in[0];
    const float* W   = (const float*)d_in[2];
    const void*  ei  = d_in[3];
    float* out = (float*)d_out;

    const int n       = in_sizes[0] / SEQ_STRIDE;   // 100000
    const int n_edges = in_sizes[3] / 2;            // 1600000

    prep_kernel<<<800, 512>>>(sem, (const long long*)ei, (long long)n, n);

    int eb = (n_edges + 511) / 512;
    hist_kernel<<<eb, 512>>>(ei, n_edges);
    scan_kernel<<<1, SCAN_THREADS>>>(n);
    place_kernel<<<eb, 512>>>(ei, n_edges);

    const int smem_bytes = (HIDDEN * HIDDEN + HIDDEN * NPB) * (int)sizeof(float);
    cudaFuncSetAttribute(agg_gemm_gelu_kernel,
                         cudaFuncAttributeMaxDynamicSharedMemorySize,
                         smem_bytes);
    int blocks = (n + NPB - 1) / NPB;
    agg_gemm_gelu_kernel<<<blocks, TPB, smem_bytes>>>(W, out, n);
}

// round 12
// speedup vs baseline: 1.3244x; 1.3244x over previous
#include <cuda_runtime.h>
#include <cuda_fp16.h>
#include <math.h>

// Problem constants (fixed by reference setup_inputs):
//   n = 100000 nodes, seq_len = 4, hidden = 128, n_edges = 1.6M
#define MAX_N      100000
#define HIDDEN     128
#define SEQ_STRIDE (4 * 128)   // floats per node in semantics

// Scratch (device globals; no allocations allowed).
__device__ float  g_sums[MAX_N * HIDDEN];   // 51.2 MB fp32 accumulators
__device__ float  g_cntf[MAX_N];            // per-target in-degree (float)
__device__ __half g_sem16[MAX_N * HIDDEN];  // fp16 copy of sem[:,0,:]
__device__ int    g_idx_is_64;              // 1 = int64 edge_index, 0 = int32

// ---------------------------------------------------------------------------
// Kernel 0: zero g_sums/g_cntf (grid-stride) + dtype probe (block 0, warp 0).
// ---------------------------------------------------------------------------
__global__ void prep_kernel(const long long* __restrict__ ei64,
                            long long n, int n_nodes) {
    int tid = blockIdx.x * blockDim.x + threadIdx.x;
    int nt  = gridDim.x * blockDim.x;

    float4 z = make_float4(0.f, 0.f, 0.f, 0.f);
    float4* sums4 = (float4*)g_sums;
    const int n4 = n_nodes * (HIDDEN / 4);
    for (int i = tid; i < n4; i += nt) sums4[i] = z;
    for (int i = tid; i < n_nodes; i += nt) g_cntf[i] = 0.f;

    if (blockIdx.x == 0 && threadIdx.x < 32) {
        int lane = threadIdx.x;
        int bad = 0;
        #pragma unroll
        for (int i = 0; i < 8; i++) {
            long long v = ei64[lane * 8 + i];
            if (v < 0 || v >= n) bad = 1;
        }
        unsigned m = __ballot_sync(0xFFFFFFFFu, bad);
        if (lane == 0) g_idx_is_64 = (m == 0u) ? 1 : 0;
    }
}

// ---------------------------------------------------------------------------
// Kernel 1: convert sem[:,0,:] fp32 -> fp16 (halves the random gather bytes).
// ---------------------------------------------------------------------------
__global__ void cvt_kernel(const float* __restrict__ sem, int n_nodes) {
    int tid = blockIdx.x * blockDim.x + threadIdx.x;
    int nt  = gridDim.x * blockDim.x;
    const int n_oct = n_nodes * (HIDDEN / 8);
    for (int i = tid; i < n_oct; i += nt) {
        int node = i >> 4;           // 16 octs of 8 floats per node
        int oct  = i & 15;
        const float4* src = (const float4*)(sem + (size_t)node * SEQ_STRIDE + oct * 8);
        float4 a = __ldg(src);
        float4 b = __ldg(src + 1);
        __half2 h[4];
        h[0] = __floats2half2_rn(a.x, a.y);
        h[1] = __floats2half2_rn(a.z, a.w);
        h[2] = __floats2half2_rn(b.x, b.y);
        h[3] = __floats2half2_rn(b.z, b.w);
        *(uint4*)(g_sem16 + (size_t)node * HIDDEN + oct * 8) = *(uint4*)h;
    }
}

// ---------------------------------------------------------------------------
// Kernels 2+3: warp-per-edge scatter over [e_beg, e_end).
// Lane loads 8 B of the fp16 source row, converts to 4 floats, and issues one
// fire-and-forget red.global.add.v4.f32 into the fp32 accumulator row.
// Max TLP: 1 edge per warp, no loops, no inter-warp dependencies (the round-2
// structure, which remains the empirical champion).
// ---------------------------------------------------------------------------
__global__ void scatter_kernel(const void* __restrict__ ei_raw,
                               int e_beg, int e_end) {
    int e = e_beg + ((blockIdx.x * blockDim.x + threadIdx.x) >> 5);
    int lane = threadIdx.x & 31;
    if (e >= e_end) return;

    long long src, tgt;
    if (g_idx_is_64) {
        const long long* ei = (const long long*)ei_raw;
        src = __ldg(ei + 2LL * e);
        tgt = __ldg(ei + 2LL * e + 1);
    } else {
        const int* ei = (const int*)ei_raw;
        src = __ldg(ei + 2LL * e);
        tgt = __ldg(ei + 2LL * e + 1);
    }

    uint2 u = __ldg((const uint2*)(g_sem16 + (size_t)src * HIDDEN) + lane);
    float2 f0 = __half22float2(*(__half2*)&u.x);
    float2 f1 = __half22float2(*(__half2*)&u.y);

    float* dst = g_sums + (size_t)tgt * HIDDEN + lane * 4;
    asm volatile("red.global.add.v4.f32 [%0], {%1, %2, %3, %4};"
                 :: "l"(dst), "f"(f0.x), "f"(f0.y), "f"(f1.x), "f"(f1.y)
                 : "memory");

    if (lane == 0) atomicAdd(&g_cntf[tgt], 1.0f);
}

// ---------------------------------------------------------------------------
// Kernel 4: fused (sums @ W) / max(cnt,1) -> exact GELU -> out.
// (Round-2 GEMM verbatim — known good, ~50 us.)
// ---------------------------------------------------------------------------
#define RPB 8
__global__ void gemm_mean_gelu_kernel(const float* __restrict__ W,
                                      float* __restrict__ out,
                                      int n) {
    __shared__ float s[RPB][HIDDEN];
    const int r0 = blockIdx.x * RPB;
    const int j  = threadIdx.x;   // 0..127

    #pragma unroll
    for (int r = 0; r < RPB; r++) {
        int row = r0 + r;
        s[r][j] = (row < n) ? g_sums[(size_t)row * HIDDEN + j] : 0.0f;
    }
    __syncthreads();

    float acc[RPB];
    #pragma unroll
    for (int r = 0; r < RPB; r++) acc[r] = 0.0f;

    #pragma unroll 4
    for (int k = 0; k < HIDDEN; k++) {
        float w = __ldg(W + k * HIDDEN + j);
        #pragma unroll
        for (int r = 0; r < RPB; r++) acc[r] = fmaf(s[r][k], w, acc[r]);
    }

    #pragma unroll
    for (int r = 0; r < RPB; r++) {
        int row = r0 + r;
        if (row < n) {
            float c = g_cntf[row];
            float m = acc[r] / fmaxf(c, 1.0f);
            // exact GELU: 0.5*x*(1 + erf(x/sqrt(2)))
            out[(size_t)row * HIDDEN + j] =
                0.5f * m * (1.0f + erff(m * 0.70710678118654752f));
        }
    }
}

// ---------------------------------------------------------------------------
// kernel_launch: prep -> cvt -> scatter(half A) -> scatter(half B) -> gemm.
// The scatter is split so the hot kernel occupies kernel-index 3, where ncu's
// capture has consistently landed. All graph-capturable; no allocations.
// Input order (metadata): semantics, attention_masks (unused), W, edge_index.
// ---------------------------------------------------------------------------
extern "C" void kernel_launch(void* const* d_in, const int* in_sizes, int n_in,
                              void* d_out, int out_size) {
    const float* sem = (const float*)d_in[0];
    const float* W   = (const float*)d_in[2];
    const void*  ei  = d_in[3];
    float* out = (float*)d_out;

    const int n       = in_sizes[0] / SEQ_STRIDE;   // 100000
    const int n_edges = in_sizes[3] / 2;            // 1600000

    prep_kernel<<<400, 512>>>((const long long*)ei, (long long)n, n);
    cvt_kernel<<<400, 512>>>(sem, n);

    const int half = (n_edges + 1) / 2;
    // 8 edges (warps) per 256-thread block
    scatter_kernel<<<(half + 7) / 8, 256>>>(ei, 0, half);
    scatter_kernel<<<(n_edges - half + 7) / 8, 256>>>(ei, half, n_edges);

    int gb = (n + RPB - 1) / RPB;
    gemm_mean_gelu_kernel<<<gb, HIDDEN>>>(W, out, n);
}

// round 13
// speedup vs baseline: 1.5706x; 1.1859x over previous
#include <cuda_runtime.h>
#include <cuda_fp16.h>
#include <math.h>

// Problem constants (fixed by reference setup_inputs):
//   n = 100000 nodes, seq_len = 4, hidden = 128, n_edges = 1.6M
#define MAX_N      100000
#define HIDDEN     128
#define SEQ_STRIDE (4 * 128)   // floats per node in semantics

// Scratch (device globals; no allocations allowed).
__device__ float  g_sums[MAX_N * HIDDEN];   // 51.2 MB fp32 accumulators
__device__ float  g_cntf[MAX_N];            // per-target in-degree (float)
__device__ __half g_sem16[MAX_N * HIDDEN];  // fp16 copy of sem[:,0,:]
__device__ int    g_idx_is_64;              // 1 = int64 edge_index, 0 = int32

// ---------------------------------------------------------------------------
// Kernel 0: zero g_sums/g_cntf (grid-stride) + dtype probe (block 0, warp 0).
// ---------------------------------------------------------------------------
__global__ void prep_kernel(const long long* __restrict__ ei64,
                            long long n, int n_nodes) {
    int tid = blockIdx.x * blockDim.x + threadIdx.x;
    int nt  = gridDim.x * blockDim.x;

    float4 z = make_float4(0.f, 0.f, 0.f, 0.f);
    float4* sums4 = (float4*)g_sums;
    const int n4 = n_nodes * (HIDDEN / 4);
    for (int i = tid; i < n4; i += nt) sums4[i] = z;
    for (int i = tid; i < n_nodes; i += nt) g_cntf[i] = 0.f;

    if (blockIdx.x == 0 && threadIdx.x < 32) {
        int lane = threadIdx.x;
        int bad = 0;
        #pragma unroll
        for (int i = 0; i < 8; i++) {
            long long v = ei64[lane * 8 + i];
            if (v < 0 || v >= n) bad = 1;
        }
        unsigned m = __ballot_sync(0xFFFFFFFFu, bad);
        if (lane == 0) g_idx_is_64 = (m == 0u) ? 1 : 0;
    }
}

// ---------------------------------------------------------------------------
// Kernel 1: convert sem[:,0,:] fp32 -> fp16 (halves the random gather bytes).
// ---------------------------------------------------------------------------
__global__ void cvt_kernel(const float* __restrict__ sem, int n_nodes) {
    int tid = blockIdx.x * blockDim.x + threadIdx.x;
    int nt  = gridDim.x * blockDim.x;
    const int n_oct = n_nodes * (HIDDEN / 8);
    for (int i = tid; i < n_oct; i += nt) {
        int node = i >> 4;           // 16 octs of 8 floats per node
        int oct  = i & 15;
        const float4* src = (const float4*)(sem + (size_t)node * SEQ_STRIDE + oct * 8);
        float4 a = __ldg(src);
        float4 b = __ldg(src + 1);
        __half2 h[4];
        h[0] = __floats2half2_rn(a.x, a.y);
        h[1] = __floats2half2_rn(a.z, a.w);
        h[2] = __floats2half2_rn(b.x, b.y);
        h[3] = __floats2half2_rn(b.z, b.w);
        *(uint4*)(g_sem16 + (size_t)node * HIDDEN + oct * 8) = *(uint4*)h;
    }
}

// ---------------------------------------------------------------------------
// Kernels 2+3: scatter, 4 independent edges per warp.
// Batch the 4 index loads, then issue 4 INDEPENDENT row loads (MLP=4 on the
// long-latency chain), then 4 REDs. Lanes 0-3 do the count atomics in
// parallel. Fixes the measured latency exposure (L1 58%, issue 35%).
// ---------------------------------------------------------------------------
#define EPW 4   // edges per warp
__global__ void scatter_kernel(const void* __restrict__ ei_raw,
                               int e_beg, int e_end) {
    const int warp = (blockIdx.x * blockDim.x + threadIdx.x) >> 5;
    const int lane = threadIdx.x & 31;
    const int e0 = e_beg + warp * EPW;
    if (e0 >= e_end) return;

    const int m = min(EPW, e_end - e0);

    int srcs[EPW], tgts[EPW];
    if (g_idx_is_64) {
        const longlong2* ei = (const longlong2*)ei_raw;
        #pragma unroll
        for (int u = 0; u < EPW; u++) {
            longlong2 p = __ldg(ei + e0 + (u < m ? u : 0));
            srcs[u] = (int)p.x; tgts[u] = (int)p.y;
        }
    } else {
        const int2* ei = (const int2*)ei_raw;
        #pragma unroll
        for (int u = 0; u < EPW; u++) {
            int2 p = __ldg(ei + e0 + (u < m ? u : 0));
            srcs[u] = p.x; tgts[u] = p.y;
        }
    }

    // 4 independent 256 B row loads (8 B/lane each).
    uint2 v[EPW];
    #pragma unroll
    for (int u = 0; u < EPW; u++)
        v[u] = __ldg((const uint2*)(g_sem16 + (size_t)srcs[u] * HIDDEN) + lane);

    #pragma unroll
    for (int u = 0; u < EPW; u++) {
        if (u < m) {
            float2 f0 = __half22float2(*(__half2*)&v[u].x);
            float2 f1 = __half22float2(*(__half2*)&v[u].y);
            float* dst = g_sums + (size_t)tgts[u] * HIDDEN + lane * 4;
            asm volatile("red.global.add.v4.f32 [%0], {%1, %2, %3, %4};"
                         :: "l"(dst), "f"(f0.x), "f"(f0.y), "f"(f1.x), "f"(f1.y)
                         : "memory");
        }
    }

    // Parallel count atomics: lane u handles edge u.
    if (lane < m) atomicAdd(&g_cntf[tgts[lane]], 1.0f);
}

// ---------------------------------------------------------------------------
// Kernel 4: fused (sums @ W) / max(cnt,1) -> exact GELU -> out.
// RPB=16 + float4 s-tiles: one broadcast LDS.128 feeds 4 FMAs (was 1 LDS per
// FMA), and W LDG count is halved vs RPB=8.
// ---------------------------------------------------------------------------
#define RPB 16
__global__ void gemm_mean_gelu_kernel(const float* __restrict__ W,
                                      float* __restrict__ out,
                                      int n) {
    __shared__ float4 s4[RPB][HIDDEN / 4];   // s[r][4kq..4kq+3]
    const int r0 = blockIdx.x * RPB;
    const int j  = threadIdx.x;   // 0..127 output column

    const float4 z = make_float4(0.f, 0.f, 0.f, 0.f);
    for (int i = threadIdx.x; i < RPB * (HIDDEN / 4); i += HIDDEN) {
        int r  = i >> 5;          // /(HIDDEN/4)
        int kq = i & 31;
        int row = r0 + r;
        s4[r][kq] = (row < n)
            ? ((const float4*)(g_sums + (size_t)row * HIDDEN))[kq] : z;
    }
    __syncthreads();

    float acc[RPB];
    #pragma unroll
    for (int r = 0; r < RPB; r++) acc[r] = 0.0f;

    #pragma unroll 4
    for (int kq = 0; kq < HIDDEN / 4; kq++) {
        const float w0 = __ldg(W + (4 * kq + 0) * HIDDEN + j);
        const float w1 = __ldg(W + (4 * kq + 1) * HIDDEN + j);
        const float w2 = __ldg(W + (4 * kq + 2) * HIDDEN + j);
        const float w3 = __ldg(W + (4 * kq + 3) * HIDDEN + j);
        #pragma unroll
        for (int r = 0; r < RPB; r++) {
            float4 sv = s4[r][kq];        // broadcast LDS.128
            acc[r] = fmaf(sv.x, w0, acc[r]);
            acc[r] = fmaf(sv.y, w1, acc[r]);
            acc[r] = fmaf(sv.z, w2, acc[r]);
            acc[r] = fmaf(sv.w, w3, acc[r]);
        }
    }

    #pragma unroll
    for (int r = 0; r < RPB; r++) {
        int row = r0 + r;
        if (row < n) {
            float c = g_cntf[row];
            float m = acc[r] / fmaxf(c, 1.0f);
            // exact GELU: 0.5*x*(1 + erf(x/sqrt(2)))
            out[(size_t)row * HIDDEN + j] =
                0.5f * m * (1.0f + erff(m * 0.70710678118654752f));
        }
    }
}

// ---------------------------------------------------------------------------
// kernel_launch: prep -> cvt -> scatter(half A) -> scatter(half B) -> gemm.
// Scatter split keeps the hot kernel at ncu's capture slot (index 3).
// All graph-capturable; no allocations.
// Input order (metadata): semantics, attention_masks (unused), W, edge_index.
// ---------------------------------------------------------------------------
extern "C" void kernel_launch(void* const* d_in, const int* in_sizes, int n_in,
                              void* d_out, int out_size) {
    const float* sem = (const float*)d_in[0];
    const float* W   = (const float*)d_in[2];
    const void*  ei  = d_in[3];
    float* out = (float*)d_out;

    const int n       = in_sizes[0] / SEQ_STRIDE;   // 100000
    const int n_edges = in_sizes[3] / 2;            // 1600000

    prep_kernel<<<400, 512>>>((const long long*)ei, (long long)n, n);
    cvt_kernel<<<400, 512>>>(sem, n);

    const int half = (n_edges + 1) / 2;
    // 8 warps/block, EPW edges per warp
    const int epb = 8 * EPW;
    scatter_kernel<<<(half + epb - 1) / epb, 256>>>(ei, 0, half);
    scatter_kernel<<<(n_edges - half + epb - 1) / epb, 256>>>(ei, half, n_edges);

    int gb = (n + RPB - 1) / RPB;
    gemm_mean_gelu_kernel<<<gb, HIDDEN>>>(W, out, n);
}

// round 14
// speedup vs baseline: 1.5927x; 1.0140x over previous
#include <cuda_runtime.h>
#include <cuda_fp16.h>
#include <math.h>

// Problem constants (fixed by reference setup_inputs):
//   n = 100000 nodes, seq_len = 4, hidden = 128, n_edges = 1.6M
#define MAX_N      100000
#define HIDDEN     128
#define SEQ_STRIDE (4 * 128)   // floats per node in semantics

// Scratch (device globals; no allocations allowed).
__device__ float  g_sums[MAX_N * HIDDEN];   // 51.2 MB fp32 accumulators
__device__ float  g_cntf[MAX_N];            // per-target in-degree (float)
__device__ __half g_sem16[MAX_N * HIDDEN];  // fp16 copy of sem[:,0,:]
__device__ int    g_idx_is_64;              // 1 = int64 edge_index, 0 = int32

// ---------------------------------------------------------------------------
// f32x2 helpers (fma.rn.f32x2 — 2 FMA per issue slot).
// ---------------------------------------------------------------------------
__device__ __forceinline__ unsigned long long pack_f32x2(float lo, float hi) {
    unsigned long long r;
    asm("mov.b64 %0, {%1, %2};" : "=l"(r) : "f"(lo), "f"(hi));
    return r;
}
__device__ __forceinline__ void fma_f32x2(unsigned long long& d,
                                          unsigned long long a,
                                          unsigned long long b) {
    asm("fma.rn.f32x2 %0, %1, %2, %0;" : "+l"(d) : "l"(a), "l"(b));
}
__device__ __forceinline__ float hsum_f32x2(unsigned long long v) {
    float lo, hi;
    asm("mov.b64 {%0, %1}, %2;" : "=f"(lo), "=f"(hi) : "l"(v));
    return lo + hi;
}

// ---------------------------------------------------------------------------
// Kernel 0: zero g_sums/g_cntf (grid-stride) + dtype probe (block 0, warp 0).
// ---------------------------------------------------------------------------
__global__ void prep_kernel(const long long* __restrict__ ei64,
                            long long n, int n_nodes) {
    int tid = blockIdx.x * blockDim.x + threadIdx.x;
    int nt  = gridDim.x * blockDim.x;

    float4 z = make_float4(0.f, 0.f, 0.f, 0.f);
    float4* sums4 = (float4*)g_sums;
    const int n4 = n_nodes * (HIDDEN / 4);
    for (int i = tid; i < n4; i += nt) sums4[i] = z;
    for (int i = tid; i < n_nodes; i += nt) g_cntf[i] = 0.f;

    if (blockIdx.x == 0 && threadIdx.x < 32) {
        int lane = threadIdx.x;
        int bad = 0;
        #pragma unroll
        for (int i = 0; i < 8; i++) {
            long long v = ei64[lane * 8 + i];
            if (v < 0 || v >= n) bad = 1;
        }
        unsigned m = __ballot_sync(0xFFFFFFFFu, bad);
        if (lane == 0) g_idx_is_64 = (m == 0u) ? 1 : 0;
    }
}

// ---------------------------------------------------------------------------
// Kernel 1: convert sem[:,0,:] fp32 -> fp16 (halves the random gather bytes).
// ---------------------------------------------------------------------------
__global__ void cvt_kernel(const float* __restrict__ sem, int n_nodes) {
    int tid = blockIdx.x * blockDim.x + threadIdx.x;
    int nt  = gridDim.x * blockDim.x;
    const int n_oct = n_nodes * (HIDDEN / 8);
    for (int i = tid; i < n_oct; i += nt) {
        int node = i >> 4;           // 16 octs of 8 floats per node
        int oct  = i & 15;
        const float4* src = (const float4*)(sem + (size_t)node * SEQ_STRIDE + oct * 8);
        float4 a = __ldg(src);
        float4 b = __ldg(src + 1);
        __half2 h[4];
        h[0] = __floats2half2_rn(a.x, a.y);
        h[1] = __floats2half2_rn(a.z, a.w);
        h[2] = __floats2half2_rn(b.x, b.y);
        h[3] = __floats2half2_rn(b.z, b.w);
        *(uint4*)(g_sem16 + (size_t)node * HIDDEN + oct * 8) = *(uint4*)h;
    }
}

// ---------------------------------------------------------------------------
// Kernels 2+3: scatter, 8 independent edges per warp (MLP=8 on the dependent
// idx->row chain, which R13 proved is the binder: L1 75%, issue 24%).
// ---------------------------------------------------------------------------
#define EPW 8   // edges per warp
__global__ void scatter_kernel(const void* __restrict__ ei_raw,
                               int e_beg, int e_end) {
    const int warp = (blockIdx.x * blockDim.x + threadIdx.x) >> 5;
    const int lane = threadIdx.x & 31;
    const int e0 = e_beg + warp * EPW;
    if (e0 >= e_end) return;

    const int m = min(EPW, e_end - e0);

    int srcs[EPW], tgts[EPW];
    if (g_idx_is_64) {
        const longlong2* ei = (const longlong2*)ei_raw;
        #pragma unroll
        for (int u = 0; u < EPW; u++) {
            longlong2 p = __ldg(ei + e0 + (u < m ? u : 0));
            srcs[u] = (int)p.x; tgts[u] = (int)p.y;
        }
    } else {
        const int2* ei = (const int2*)ei_raw;
        #pragma unroll
        for (int u = 0; u < EPW; u++) {
            int2 p = __ldg(ei + e0 + (u < m ? u : 0));
            srcs[u] = p.x; tgts[u] = p.y;
        }
    }

    // 8 independent 256 B row loads (8 B/lane each).
    uint2 v[EPW];
    #pragma unroll
    for (int u = 0; u < EPW; u++)
        v[u] = __ldg((const uint2*)(g_sem16 + (size_t)srcs[u] * HIDDEN) + lane);

    #pragma unroll
    for (int u = 0; u < EPW; u++) {
        if (u < m) {
            float2 f0 = __half22float2(*(__half2*)&v[u].x);
            float2 f1 = __half22float2(*(__half2*)&v[u].y);
            float* dst = g_sums + (size_t)tgts[u] * HIDDEN + lane * 4;
            asm volatile("red.global.add.v4.f32 [%0], {%1, %2, %3, %4};"
                         :: "l"(dst), "f"(f0.x), "f"(f0.y), "f"(f1.x), "f"(f1.y)
                         : "memory");
        }
    }

    // Parallel count atomics: lane u handles edge u.
    if (lane < m) atomicAdd(&g_cntf[tgts[lane]], 1.0f);
}

// ---------------------------------------------------------------------------
// Kernel 4: fused (sums @ W) / max(cnt,1) -> exact GELU -> out.
// RPB=16, k-pairs packed into fma.rn.f32x2 (halves the measured ~98 us of
// scalar-FFMA issue); one broadcast LDS.128 feeds 2 FFMA2.
// ---------------------------------------------------------------------------
#define RPB 16
__global__ void gemm_mean_gelu_kernel(const float* __restrict__ W,
                                      float* __restrict__ out,
                                      int n) {
    __shared__ float4 s4[RPB][HIDDEN / 4];   // s[r][4kq..4kq+3]
    const int r0 = blockIdx.x * RPB;
    const int j  = threadIdx.x;   // 0..127 output column

    const float4 z = make_float4(0.f, 0.f, 0.f, 0.f);
    for (int i = threadIdx.x; i < RPB * (HIDDEN / 4); i += HIDDEN) {
        int r  = i >> 5;          // /(HIDDEN/4)
        int kq = i & 31;
        int row = r0 + r;
        s4[r][kq] = (row < n)
            ? ((const float4*)(g_sums + (size_t)row * HIDDEN))[kq] : z;
    }
    __syncthreads();

    unsigned long long acc2[RPB];
    #pragma unroll
    for (int r = 0; r < RPB; r++) acc2[r] = 0ull;

    #pragma unroll 4
    for (int kq = 0; kq < HIDDEN / 4; kq++) {
        const float w0 = __ldg(W + (4 * kq + 0) * HIDDEN + j);
        const float w1 = __ldg(W + (4 * kq + 1) * HIDDEN + j);
        const float w2 = __ldg(W + (4 * kq + 2) * HIDDEN + j);
        const float w3 = __ldg(W + (4 * kq + 3) * HIDDEN + j);
        const unsigned long long w01 = pack_f32x2(w0, w1);
        const unsigned long long w23 = pack_f32x2(w2, w3);
        #pragma unroll
        for (int r = 0; r < RPB; r++) {
            float4 sv = s4[r][kq];        // broadcast LDS.128
            const unsigned long long* sp = (const unsigned long long*)&sv;
            fma_f32x2(acc2[r], sp[0], w01);
            fma_f32x2(acc2[r], sp[1], w23);
        }
    }

    #pragma unroll
    for (int r = 0; r < RPB; r++) {
        int row = r0 + r;
        if (row < n) {
            float c = g_cntf[row];
            float m = hsum_f32x2(acc2[r]) / fmaxf(c, 1.0f);
            // exact GELU: 0.5*x*(1 + erf(x/sqrt(2)))
            out[(size_t)row * HIDDEN + j] =
                0.5f * m * (1.0f + erff(m * 0.70710678118654752f));
        }
    }
}

// ---------------------------------------------------------------------------
// kernel_launch: prep -> cvt -> scatter(half A) -> scatter(half B) -> gemm.
// Scatter split keeps the hot kernel at ncu's capture slot (index 3).
// All graph-capturable; no allocations.
// Input order (metadata): semantics, attention_masks (unused), W, edge_index.
// ---------------------------------------------------------------------------
extern "C" void kernel_launch(void* const* d_in, const int* in_sizes, int n_in,
                              void* d_out, int out_size) {
    const float* sem = (const float*)d_in[0];
    const float* W   = (const float*)d_in[2];
    const void*  ei  = d_in[3];
    float* out = (float*)d_out;

    const int n       = in_sizes[0] / SEQ_STRIDE;   // 100000
    const int n_edges = in_sizes[3] / 2;            // 1600000

    prep_kernel<<<400, 512>>>((const long long*)ei, (long long)n, n);
    cvt_kernel<<<400, 512>>>(sem, n);

    const int half = (n_edges + 1) / 2;
    // 8 warps/block, EPW edges per warp
    const int epb = 8 * EPW;
    scatter_kernel<<<(half + epb - 1) / epb, 256>>>(ei, 0, half);
    scatter_kernel<<<(n_edges - half + epb - 1) / epb, 256>>>(ei, half, n_edges);

    int gb = (n + RPB - 1) / RPB;
    gemm_mean_gelu_kernel<<<gb, HIDDEN>>>(W, out, n);
}